// round 10
// baseline (speedup 1.0000x reference)
#include <cuda_runtime.h>
#include <math.h>
#include <stdint.h>

#define BB 4
#define SS 1024
#define DD 1024
#define HH 16
#define HDIM 64
#define FF 4096
#define NROWS (BB*SS)           // 4096
#define NHEADS (BB*HH)          // 64
#define LN_EPS 1e-5f
#define ATT_SCALE 0.125f        // 1/sqrt(64)

// ---------------- scratch (static device arrays; no cudaMalloc allowed) --------------
__device__ float g_y [NROWS*DD];   // ln1 out, later attention output
__device__ float g_q [NROWS*DD];   // Q, later x2 (post-FFN residual)
__device__ float g_k [NROWS*DD];
__device__ float g_v [NROWS*DD];
__device__ float g_x1[NROWS*DD];   // post-attention residual
__device__ float g_h [NROWS*FF];   // FFN hidden
__device__ float g_wt[8*1024*1024]; // transposed weights: wqT,wkT,wvT,woT @ 0..3M, big @ 4M

#define WT_Q 0
#define WT_K (1024*1024)
#define WT_V (2*1024*1024)
#define WT_O (3*1024*1024)
#define WT_BIG (4*1024*1024)

// ---------------- helpers ----------------
__device__ __forceinline__ float warpSum(float v) {
#pragma unroll
    for (int o = 16; o > 0; o >>= 1) v += __shfl_xor_sync(0xffffffffu, v, o);
    return v;
}
__device__ __forceinline__ float warpMax(float v) {
#pragma unroll
    for (int o = 16; o > 0; o >>= 1) v = fmaxf(v, __shfl_xor_sync(0xffffffffu, v, o));
    return v;
}
__device__ __forceinline__ uint32_t f2tf32(float x) {
    uint32_t r;
    asm("cvt.rna.tf32.f32 %0, %1;" : "=r"(r) : "f"(x));
    return r;
}
__device__ __forceinline__ void mma_tf32(float* c, const uint32_t* a, const uint32_t* b) {
    asm volatile(
        "mma.sync.aligned.m16n8k8.row.col.f32.tf32.tf32.f32 "
        "{%0,%1,%2,%3}, {%4,%5,%6,%7}, {%8,%9}, {%0,%1,%2,%3};\n"
        : "+f"(c[0]), "+f"(c[1]), "+f"(c[2]), "+f"(c[3])
        : "r"(a[0]), "r"(a[1]), "r"(a[2]), "r"(a[3]), "r"(b[0]), "r"(b[1]));
}
__device__ __forceinline__ void ldsm_x4(uint32_t* r, uint32_t addr) {
    asm volatile("ldmatrix.sync.aligned.m8n8.x4.shared.b16 {%0,%1,%2,%3}, [%4];"
                 : "=r"(r[0]), "=r"(r[1]), "=r"(r[2]), "=r"(r[3]) : "r"(addr));
}

// ---------------- weight transpose: out[n][k] = in[k][n] -----------------------------
__global__ void transpose_kernel(const float* __restrict__ in, float* __restrict__ out,
                                 int K, int N) {
    __shared__ float tile[32][33];
    int k0 = blockIdx.y * 32, n0 = blockIdx.x * 32;
    int tx = threadIdx.x, ty = threadIdx.y;      // 32 x 8
#pragma unroll
    for (int i = 0; i < 4; i++)
        tile[ty + i * 8][tx] = in[(size_t)(k0 + ty + i * 8) * N + n0 + tx];
    __syncthreads();
#pragma unroll
    for (int i = 0; i < 4; i++)
        out[(size_t)(n0 + ty + i * 8) * K + k0 + tx] = tile[tx][ty + i * 8];
}

// ---------------- LayerNorm over D=1024, one block (256 thr) per row -----------------
__global__ void ln_kernel(const float* __restrict__ in, const float* __restrict__ g,
                          const float* __restrict__ b, float* __restrict__ out) {
    int row = blockIdx.x;
    const float* x = in + (size_t)row * DD;
    int t = threadIdx.x, lane = t & 31, wid = t >> 5;
    float v[4];
#pragma unroll
    for (int i = 0; i < 4; i++) v[i] = x[t + 256 * i];
    float s = v[0] + v[1] + v[2] + v[3];
    float ss = v[0]*v[0] + v[1]*v[1] + v[2]*v[2] + v[3]*v[3];
    s = warpSum(s); ss = warpSum(ss);
    __shared__ float rA[8], rB[8];
    if (lane == 0) { rA[wid] = s; rB[wid] = ss; }
    __syncthreads();
    s  = (lane < 8) ? rA[lane] : 0.f;
    ss = (lane < 8) ? rB[lane] : 0.f;
    s = warpSum(s); ss = warpSum(ss);
    float mean = s * (1.f / DD);
    float var  = ss * (1.f / DD) - mean * mean;
    float rstd = rsqrtf(var + LN_EPS);
    float* o = out + (size_t)row * DD;
#pragma unroll
    for (int i = 0; i < 4; i++) {
        int c = t + 256 * i;
        o[c] = (v[i] - mean) * rstd * g[c] + b[c];
    }
}

__device__ __forceinline__ float mishf(float x) {
    float sp = (x > 20.f) ? x : log1pf(expf(x));
    return x * tanhf(sp);
}

// ---------------- tf32 GEMM, both operands via ldmatrix ------------------------------
// Block tile 128x128, BK=32. 8 warps in 2(m) x 4(n): each warp 64x32 = 4x4 m16n8k8.
// As: [m][k] tf32, pitch 36.  Bs: [n][k] tf32, pitch 36 (staged from Wt = W^T [N][K]).
// Both ldmatrix geometries: row stride 9x16B (mod 8 = 1) -> conflict-free.
template <int EPI>
__global__ __launch_bounds__(256)
void tgemm_kernel(const float* __restrict__ A, const float* __restrict__ Wt,
                  const float* __restrict__ bias, const float* __restrict__ resid,
                  float* __restrict__ C, int M, int N, int K) {
    __shared__ uint32_t As[128][36];   // [m][k]
    __shared__ uint32_t Bs[128][36];   // [n][k]
    int tid = threadIdx.x, lane = tid & 31, wid = tid >> 5;
    int g = lane >> 2, tig = lane & 3;
    int wm = (wid >> 2) * 64, wn = (wid & 3) * 32;
    int bm = blockIdx.y * 128, bn = blockIdx.x * 128;

    float acc[4][4][4];
#pragma unroll
    for (int mt = 0; mt < 4; mt++)
#pragma unroll
        for (int nt = 0; nt < 4; nt++)
#pragma unroll
            for (int i = 0; i < 4; i++) acc[mt][nt][i] = 0.f;

    // staging: 128 rows x 32 cols each, 2 threads/row, 16 floats/thread
    int sRow = tid >> 1, sCol0 = (tid & 1) * 16;
    const float* Agp = A  + (size_t)(bm + sRow) * K + sCol0;
    const float* Wgp = Wt + (size_t)(bn + sRow) * K + sCol0;

    // ldmatrix bases
    uint32_t aLdsmBase = (uint32_t)__cvta_generic_to_shared(
        &As[wm + (lane & 15)][(lane >> 4) * 4]);
    int bq = lane >> 3;
    uint32_t bLdsmBase0 = (uint32_t)__cvta_generic_to_shared(
        &Bs[wn + (bq >> 1) * 8 + (lane & 7)][(bq & 1) * 4]);
    uint32_t bLdsmBase1 = bLdsmBase0 + 16u * 36u * 4u;   // +16 n-rows

    for (int k0 = 0; k0 < K; k0 += 32) {
#pragma unroll
        for (int p = 0; p < 4; p++) {
            float4 av = *(const float4*)(Agp + k0 + p * 4);
            uint4 u;
            u.x = f2tf32(av.x); u.y = f2tf32(av.y);
            u.z = f2tf32(av.z); u.w = f2tf32(av.w);
            *(uint4*)&As[sRow][sCol0 + p * 4] = u;
        }
#pragma unroll
        for (int p = 0; p < 4; p++) {
            float4 bv = *(const float4*)(Wgp + k0 + p * 4);
            uint4 u;
            u.x = f2tf32(bv.x); u.y = f2tf32(bv.y);
            u.z = f2tf32(bv.z); u.w = f2tf32(bv.w);
            *(uint4*)&Bs[sRow][sCol0 + p * 4] = u;
        }
        __syncthreads();
#pragma unroll
        for (int kt = 0; kt < 4; kt++) {
            int kb = kt * 8;
            uint32_t af[4][4], bf[4][2];
#pragma unroll
            for (int mt = 0; mt < 4; mt++)
                ldsm_x4(af[mt], aLdsmBase + (uint32_t)(mt * 16 * 36 + kb) * 4u);
            {
                uint32_t r[4];
                ldsm_x4(r, bLdsmBase0 + (uint32_t)kb * 4u);
                bf[0][0] = r[0]; bf[0][1] = r[1]; bf[1][0] = r[2]; bf[1][1] = r[3];
                ldsm_x4(r, bLdsmBase1 + (uint32_t)kb * 4u);
                bf[2][0] = r[0]; bf[2][1] = r[1]; bf[3][0] = r[2]; bf[3][1] = r[3];
            }
#pragma unroll
            for (int mt = 0; mt < 4; mt++)
#pragma unroll
                for (int nt = 0; nt < 4; nt++)
                    mma_tf32(acc[mt][nt], af[mt], bf[nt]);
        }
        __syncthreads();
    }

    // epilogue: c0:(g,tig*2) c1:(g,tig*2+1) c2:(g+8,tig*2) c3:(g+8,tig*2+1)
#pragma unroll
    for (int mt = 0; mt < 4; mt++) {
        int row0 = bm + wm + mt * 16 + g;
#pragma unroll
        for (int nt = 0; nt < 4; nt++) {
            int col = bn + wn + nt * 8 + tig * 2;
            float b0 = bias[col], b1 = bias[col + 1];
#pragma unroll
            for (int half = 0; half < 2; half++) {
                int row = row0 + half * 8;
                float v0 = acc[mt][nt][half * 2 + 0] + b0;
                float v1 = acc[mt][nt][half * 2 + 1] + b1;
                if (EPI == 1) { v0 = mishf(v0); v1 = mishf(v1); }
                if (EPI == 2) {
                    v0 += resid[(size_t)row * N + col];
                    v1 += resid[(size_t)row * N + col + 1];
                }
                C[(size_t)row * N + col]     = v0;
                C[(size_t)row * N + col + 1] = v1;
            }
        }
    }
}

// ---------------- fused attention: tf32 MMA scores + 1.5-entmax + tf32 MMA P@V ------
// (validated at R7/R9; unchanged)
#define ATT_PITCH 1028
#define ATT_SC_FLOATS (32*ATT_PITCH)              // 32896
#define ATT_QS_OFF ATT_SC_FLOATS
#define ATT_KV_OFF (ATT_QS_OFF + 32*68)           // 35072
#define ATT_SMEM_FLOATS (ATT_KV_OFF + 128*72)     // 44288
#define ATTN_SMEM_BYTES (ATT_SMEM_FLOATS*4)       // 177152
#define RED_PITCH 68
#define RED_WSTR (32*RED_PITCH)                   // 2176

__global__ __launch_bounds__(256)
void attn_kernel(const float* __restrict__ Q, const float* __restrict__ Kg,
                 const float* __restrict__ V, float* __restrict__ O) {
    extern __shared__ float sm[];
    float* sc = sm;                                    // [32][1028]
    uint32_t* qs  = (uint32_t*)(sm + ATT_QS_OFF);      // [32][68] tf32 (m-major)
    uint32_t* kvs = (uint32_t*)(sm + ATT_KV_OFF);      // K:[64][136] / V:[128][72] tf32

    int bh = blockIdx.y; int b = bh >> 4, h = bh & 15;
    int m0 = blockIdx.x * 32;
    const float* Qb = Q + (size_t)b * SS * DD + h * HDIM;
    const float* Kb = Kg + (size_t)b * SS * DD + h * HDIM;
    const float* Vb = V + (size_t)b * SS * DD + h * HDIM;

    int t = threadIdx.x, lane = t & 31, w = t >> 5;
    int g = lane >> 2, tig = lane & 3;

    // ---- stage Q (32x64) as tf32, [m][k] pitch 68 ----
    {
        int row = t >> 3, cb = (t & 7) * 8;
        const float* Qr = Qb + (size_t)(m0 + row) * DD + cb;
#pragma unroll
        for (int i = 0; i < 2; i++) {
            float4 qv = *(const float4*)(Qr + i * 4);
            qs[row * 68 + cb + i * 4 + 0] = f2tf32(qv.x);
            qs[row * 68 + cb + i * 4 + 1] = f2tf32(qv.y);
            qs[row * 68 + cb + i * 4 + 2] = f2tf32(qv.z);
            qs[row * 68 + cb + i * 4 + 3] = f2tf32(qv.w);
        }
    }
    __syncthreads();

    // ---- phase 1: S = scale * Q K^T via MMA; warp w owns cols [w*16, w*16+16) ----
    for (int n0 = 0; n0 < SS; n0 += 128) {
        {
            int n = t & 127, dh = (t >> 7) * 32;
            const float* Kr = Kb + (size_t)(n0 + n) * DD + dh;
#pragma unroll
            for (int i = 0; i < 8; i++) {
                float4 kvv = *(const float4*)(Kr + i * 4);
                kvs[(dh + i * 4 + 0) * 136 + n] = f2tf32(kvv.x);
                kvs[(dh + i * 4 + 1) * 136 + n] = f2tf32(kvv.y);
                kvs[(dh + i * 4 + 2) * 136 + n] = f2tf32(kvv.z);
                kvs[(dh + i * 4 + 3) * 136 + n] = f2tf32(kvv.w);
            }
        }
        __syncthreads();
        float acc[2][2][4];
#pragma unroll
        for (int mt = 0; mt < 2; mt++)
#pragma unroll
            for (int nt = 0; nt < 2; nt++)
#pragma unroll
                for (int i = 0; i < 4; i++) acc[mt][nt][i] = 0.f;
        int nb = w * 16;
#pragma unroll
        for (int ks = 0; ks < 8; ks++) {
            int kb = ks * 8;
            uint32_t af[2][4], bf[2][2];
#pragma unroll
            for (int mt = 0; mt < 2; mt++) {
                int row = mt * 16 + g;
                af[mt][0] = qs[row * 68 + kb + tig];
                af[mt][1] = qs[(row + 8) * 68 + kb + tig];
                af[mt][2] = qs[row * 68 + kb + tig + 4];
                af[mt][3] = qs[(row + 8) * 68 + kb + tig + 4];
            }
#pragma unroll
            for (int nt = 0; nt < 2; nt++) {
                int n = nb + nt * 8 + g;
                bf[nt][0] = kvs[(kb + tig) * 136 + n];
                bf[nt][1] = kvs[(kb + tig + 4) * 136 + n];
            }
#pragma unroll
            for (int mt = 0; mt < 2; mt++)
#pragma unroll
                for (int nt = 0; nt < 2; nt++)
                    mma_tf32(acc[mt][nt], af[mt], bf[nt]);
        }
#pragma unroll
        for (int mt = 0; mt < 2; mt++) {
            int row = mt * 16 + g;
#pragma unroll
            for (int nt = 0; nt < 2; nt++) {
                int col = n0 + nb + nt * 8 + tig * 2;
                sc[row * ATT_PITCH + col]           = acc[mt][nt][0] * ATT_SCALE;
                sc[row * ATT_PITCH + col + 1]       = acc[mt][nt][1] * ATT_SCALE;
                sc[(row + 8) * ATT_PITCH + col]     = acc[mt][nt][2] * ATT_SCALE;
                sc[(row + 8) * ATT_PITCH + col + 1] = acc[mt][nt][3] * ATT_SCALE;
            }
        }
        __syncthreads();
    }

    // ---- phase 2: exact 1.5-entmax per row (warp w owns rows 4w..4w+3) ----
#pragma unroll 1
    for (int r = 0; r < 4; r++) {
        float* z = sc + (size_t)(w * 4 + r) * ATT_PITCH;
        float v[32];
#pragma unroll
        for (int i = 0; i < 32; i++) v[i] = z[lane + 32 * i];
        float m = -1e30f;
#pragma unroll
        for (int i = 0; i < 32; i++) m = fmaxf(m, v[i]);
        m = warpMax(m);
#pragma unroll
        for (int i = 0; i < 32; i++) v[i] = (v[i] - m) * 0.5f;
        float lo = -1.f, hi = 0.f;
        for (int it = 0; it < 30; it++) {
            float tau = 0.5f * (lo + hi);
            float s = 0.f;
#pragma unroll
            for (int i = 0; i < 32; i++) {
                float d = v[i] - tau;
                if (d > 0.f) s = fmaf(d, d, s);
            }
            s = warpSum(s);
            if (s >= 1.f) lo = tau; else hi = tau;
        }
        float tau = 0.5f * (lo + hi);
#pragma unroll
        for (int i = 0; i < 32; i++) {
            float d = v[i] - tau;
            d = d > 0.f ? d : 0.f;
            z[lane + 32 * i] = d * d;
        }
    }
    __syncthreads();

    // ---- phase 3: O = P V via MMA; warp w covers k-slice [w*16, w*16+16) per chunk ----
    float oacc[2][8][4];
#pragma unroll
    for (int mt = 0; mt < 2; mt++)
#pragma unroll
        for (int nt = 0; nt < 8; nt++)
#pragma unroll
            for (int i = 0; i < 4; i++) oacc[mt][nt][i] = 0.f;

    for (int c = 0; c < 8; c++) {
        int k0 = c * 128;
        {
            int r = t >> 1, ch = (t & 1) * 32;
            const float* Vr = Vb + (size_t)(k0 + r) * DD + ch;
#pragma unroll
            for (int i = 0; i < 8; i++) {
                float4 vv = *(const float4*)(Vr + i * 4);
                uint4 u;
                u.x = f2tf32(vv.x); u.y = f2tf32(vv.y);
                u.z = f2tf32(vv.z); u.w = f2tf32(vv.w);
                *(uint4*)&kvs[r * 72 + ch + i * 4] = u;
            }
        }
        __syncthreads();
#pragma unroll
        for (int s = 0; s < 2; s++) {
            int kb = w * 16 + s * 8;
            uint32_t af[2][4];
#pragma unroll
            for (int mt = 0; mt < 2; mt++) {
                int row = mt * 16 + g;
                af[mt][0] = f2tf32(sc[row * ATT_PITCH + k0 + kb + tig]);
                af[mt][1] = f2tf32(sc[(row + 8) * ATT_PITCH + k0 + kb + tig]);
                af[mt][2] = f2tf32(sc[row * ATT_PITCH + k0 + kb + tig + 4]);
                af[mt][3] = f2tf32(sc[(row + 8) * ATT_PITCH + k0 + kb + tig + 4]);
            }
#pragma unroll
            for (int nt = 0; nt < 8; nt++) {
                uint32_t bf[2];
                bf[0] = kvs[(kb + tig) * 72 + nt * 8 + g];
                bf[1] = kvs[(kb + tig + 4) * 72 + nt * 8 + g];
#pragma unroll
                for (int mt = 0; mt < 2; mt++)
                    mma_tf32(oacc[mt][nt], af[mt], bf);
            }
        }
        __syncthreads();
    }

    // ---- reduce 8 warp-partials through smem (sc is free now) ----
#pragma unroll
    for (int mt = 0; mt < 2; mt++) {
        int row = mt * 16 + g;
#pragma unroll
        for (int nt = 0; nt < 8; nt++) {
            int col = nt * 8 + tig * 2;
            float* pb = sc + w * RED_WSTR;
            pb[row * RED_PITCH + col]           = oacc[mt][nt][0];
            pb[row * RED_PITCH + col + 1]       = oacc[mt][nt][1];
            pb[(row + 8) * RED_PITCH + col]     = oacc[mt][nt][2];
            pb[(row + 8) * RED_PITCH + col + 1] = oacc[mt][nt][3];
        }
    }
    __syncthreads();
    float* Ob = O + (size_t)b * SS * DD + h * HDIM;
#pragma unroll
    for (int i = 0; i < 8; i++) {
        int idx = i * 256 + t;          // 0..2047
        int mm = idx >> 6, dd = idx & 63;
        float sum = 0.f;
#pragma unroll
        for (int ww = 0; ww < 8; ww++)
            sum += sc[ww * RED_WSTR + mm * RED_PITCH + dd];
        Ob[(size_t)(m0 + mm) * DD + dd] = sum;
    }
}

// ---------------- launch ----------------
extern "C" void kernel_launch(void* const* d_in, const int* in_sizes, int n_in,
                              void* d_out, int out_size) {
    const float* x = (const float*)d_in[0];
    const float *wq, *bq, *wk, *bk, *wv, *bv, *wo, *bo;
    if (in_sizes[2] == DD) {
        wq = (const float*)d_in[1]; bq = (const float*)d_in[2];
        wk = (const float*)d_in[3]; bk = (const float*)d_in[4];
        wv = (const float*)d_in[5]; bv = (const float*)d_in[6];
        wo = (const float*)d_in[7]; bo = (const float*)d_in[8];
    } else {
        wq = (const float*)d_in[1]; wk = (const float*)d_in[2];
        wv = (const float*)d_in[3]; wo = (const float*)d_in[4];
        bq = (const float*)d_in[5]; bk = (const float*)d_in[6];
        bv = (const float*)d_in[7]; bo = (const float*)d_in[8];
    }
    const float* w_up   = (const float*)d_in[9];
    const float* b_up   = (const float*)d_in[10];
    const float* w_down = (const float*)d_in[11];
    const float* b_down = (const float*)d_in[12];
    const float* ln1g = (const float*)d_in[13];
    const float* ln1b = (const float*)d_in[14];
    const float* ln2g = (const float*)d_in[15];
    const float* ln2b = (const float*)d_in[16];
    const float* lnfg = (const float*)d_in[17];
    const float* lnfb = (const float*)d_in[18];

    float *yp, *qp, *kp, *vp, *x1p, *hp, *wtp;
    cudaGetSymbolAddress((void**)&yp,  g_y);
    cudaGetSymbolAddress((void**)&qp,  g_q);
    cudaGetSymbolAddress((void**)&kp,  g_k);
    cudaGetSymbolAddress((void**)&vp,  g_v);
    cudaGetSymbolAddress((void**)&x1p, g_x1);
    cudaGetSymbolAddress((void**)&hp,  g_h);
    cudaGetSymbolAddress((void**)&wtp, g_wt);
    float* op  = yp;   // reuse: y dead after V projection
    float* x2p = qp;   // reuse: q dead after attention
    float* wqT = wtp + WT_Q;
    float* wkT = wtp + WT_K;
    float* wvT = wtp + WT_V;
    float* woT = wtp + WT_O;
    float* wbig = wtp + WT_BIG;   // w_upT, then reused for w_downT

    cudaFuncSetAttribute(attn_kernel, cudaFuncAttributeMaxDynamicSharedMemorySize,
                         ATTN_SMEM_BYTES);

    dim3 tb(32, 8);
    // 0. transpose attention weights
    transpose_kernel<<<dim3(DD/32, DD/32), tb>>>(wq, wqT, DD, DD);
    transpose_kernel<<<dim3(DD/32, DD/32), tb>>>(wk, wkT, DD, DD);
    transpose_kernel<<<dim3(DD/32, DD/32), tb>>>(wv, wvT, DD, DD);
    transpose_kernel<<<dim3(DD/32, DD/32), tb>>>(wo, woT, DD, DD);
    // 1. ln1
    ln_kernel<<<NROWS, 256>>>(x, ln1g, ln1b, yp);
    // 2-4. Q,K,V projections
    tgemm_kernel<0><<<dim3(8, 32), 256>>>(yp, wqT, bq, nullptr, qp, NROWS, DD, DD);
    tgemm_kernel<0><<<dim3(8, 32), 256>>>(yp, wkT, bk, nullptr, kp, NROWS, DD, DD);
    tgemm_kernel<0><<<dim3(8, 32), 256>>>(yp, wvT, bv, nullptr, vp, NROWS, DD, DD);
    // 5. fused attention (MMA scores + entmax + MMA P@V)
    attn_kernel<<<dim3(SS / 32, NHEADS), 256, ATTN_SMEM_BYTES>>>(qp, kp, vp, op);
    // 6. out proj + residual
    tgemm_kernel<2><<<dim3(8, 32), 256>>>(op, woT, bo, x, x1p, NROWS, DD, DD);
    // 7. ln2 -> k scratch (k dead)
    ln_kernel<<<NROWS, 256>>>(x1p, ln2g, ln2b, kp);
    // 8. FFN up + mish (transpose w_up first)
    transpose_kernel<<<dim3(FF/32, DD/32), tb>>>(w_up, wbig, DD, FF);
    tgemm_kernel<1><<<dim3(32, 32), 256>>>(kp, wbig, b_up, nullptr, hp, NROWS, FF, DD);
    // 9. FFN down + residual (w_upT dead; reuse wbig)
    transpose_kernel<<<dim3(DD/32, FF/32), tb>>>(w_down, wbig, FF, DD);
    tgemm_kernel<2><<<dim3(8, 32), 256>>>(hp, wbig, b_down, x1p, x2p, NROWS, DD, FF);
    // 10. final ln -> out
    ln_kernel<<<NROWS, 256>>>(x2p, lnfg, lnfb, (float*)d_out);
}

// round 11
// speedup vs baseline: 1.0068x; 1.0068x over previous
#include <cuda_runtime.h>
#include <math.h>
#include <stdint.h>

#define BB 4
#define SS 1024
#define DD 1024
#define HH 16
#define HDIM 64
#define FF 4096
#define NROWS (BB*SS)           // 4096
#define NHEADS (BB*HH)          // 64
#define LN_EPS 1e-5f
#define ATT_SCALE 0.125f        // 1/sqrt(64)

// ---------------- scratch (static device arrays; no cudaMalloc allowed) --------------
__device__ float g_y [NROWS*DD];   // ln1 out, later attention output
__device__ float g_q [NROWS*DD];   // Q, later x2 (post-FFN residual)
__device__ float g_k [NROWS*DD];
__device__ float g_v [NROWS*DD];
__device__ float g_x1[NROWS*DD];   // post-attention residual
__device__ float g_h [NROWS*FF];   // FFN hidden
__device__ float g_wt[8*1024*1024]; // transposed weights: wqT,wkT,wvT,woT @ 0..3M, big @ 4M

#define WT_Q 0
#define WT_K (1024*1024)
#define WT_V (2*1024*1024)
#define WT_O (3*1024*1024)
#define WT_BIG (4*1024*1024)

// ---------------- helpers ----------------
__device__ __forceinline__ float warpSum(float v) {
#pragma unroll
    for (int o = 16; o > 0; o >>= 1) v += __shfl_xor_sync(0xffffffffu, v, o);
    return v;
}
__device__ __forceinline__ float warpMax(float v) {
#pragma unroll
    for (int o = 16; o > 0; o >>= 1) v = fmaxf(v, __shfl_xor_sync(0xffffffffu, v, o));
    return v;
}
__device__ __forceinline__ uint32_t f2tf32(float x) {
    uint32_t r;
    asm("cvt.rna.tf32.f32 %0, %1;" : "=r"(r) : "f"(x));
    return r;
}
__device__ __forceinline__ void mma_tf32(float* c, const uint32_t* a, const uint32_t* b) {
    asm volatile(
        "mma.sync.aligned.m16n8k8.row.col.f32.tf32.tf32.f32 "
        "{%0,%1,%2,%3}, {%4,%5,%6,%7}, {%8,%9}, {%0,%1,%2,%3};\n"
        : "+f"(c[0]), "+f"(c[1]), "+f"(c[2]), "+f"(c[3])
        : "r"(a[0]), "r"(a[1]), "r"(a[2]), "r"(a[3]), "r"(b[0]), "r"(b[1]));
}
__device__ __forceinline__ void ldsm_x4(uint32_t* r, uint32_t addr) {
    asm volatile("ldmatrix.sync.aligned.m8n8.x4.shared.b16 {%0,%1,%2,%3}, [%4];"
                 : "=r"(r[0]), "=r"(r[1]), "=r"(r[2]), "=r"(r[3]) : "r"(addr));
}

// ---------------- weight transpose: out[n][k] = in[k][n] -----------------------------
__global__ void transpose_kernel(const float* __restrict__ in, float* __restrict__ out,
                                 int K, int N) {
    __shared__ float tile[32][33];
    int k0 = blockIdx.y * 32, n0 = blockIdx.x * 32;
    int tx = threadIdx.x, ty = threadIdx.y;      // 32 x 8
#pragma unroll
    for (int i = 0; i < 4; i++)
        tile[ty + i * 8][tx] = in[(size_t)(k0 + ty + i * 8) * N + n0 + tx];
    __syncthreads();
#pragma unroll
    for (int i = 0; i < 4; i++)
        out[(size_t)(n0 + ty + i * 8) * K + k0 + tx] = tile[tx][ty + i * 8];
}

// ---------------- LayerNorm over D=1024, one block (256 thr) per row -----------------
__global__ void ln_kernel(const float* __restrict__ in, const float* __restrict__ g,
                          const float* __restrict__ b, float* __restrict__ out) {
    int row = blockIdx.x;
    const float* x = in + (size_t)row * DD;
    int t = threadIdx.x, lane = t & 31, wid = t >> 5;
    float v[4];
#pragma unroll
    for (int i = 0; i < 4; i++) v[i] = x[t + 256 * i];
    float s = v[0] + v[1] + v[2] + v[3];
    float ss = v[0]*v[0] + v[1]*v[1] + v[2]*v[2] + v[3]*v[3];
    s = warpSum(s); ss = warpSum(ss);
    __shared__ float rA[8], rB[8];
    if (lane == 0) { rA[wid] = s; rB[wid] = ss; }
    __syncthreads();
    s  = (lane < 8) ? rA[lane] : 0.f;
    ss = (lane < 8) ? rB[lane] : 0.f;
    s = warpSum(s); ss = warpSum(ss);
    float mean = s * (1.f / DD);
    float var  = ss * (1.f / DD) - mean * mean;
    float rstd = rsqrtf(var + LN_EPS);
    float* o = out + (size_t)row * DD;
#pragma unroll
    for (int i = 0; i < 4; i++) {
        int c = t + 256 * i;
        o[c] = (v[i] - mean) * rstd * g[c] + b[c];
    }
}

__device__ __forceinline__ float mishf(float x) {
    float sp = (x > 20.f) ? x : log1pf(expf(x));
    return x * tanhf(sp);
}

// ---------------- tf32 GEMM, both operands via ldmatrix ------------------------------
// Block tile 128x128, BK=32. 8 warps in 2(m) x 4(n): each warp 64x32 = 4x4 m16n8k8.
// As: [m][k] tf32, pitch 36.  Bs: [n][k] tf32, pitch 36 (staged from Wt = W^T [N][K]).
// Both ldmatrix geometries: row stride 9x16B (mod 8 = 1) -> conflict-free.
template <int EPI>
__global__ __launch_bounds__(256)
void tgemm_kernel(const float* __restrict__ A, const float* __restrict__ Wt,
                  const float* __restrict__ bias, const float* __restrict__ resid,
                  float* __restrict__ C, int M, int N, int K) {
    __shared__ uint32_t As[128][36];   // [m][k]
    __shared__ uint32_t Bs[128][36];   // [n][k]
    int tid = threadIdx.x, lane = tid & 31, wid = tid >> 5;
    int g = lane >> 2, tig = lane & 3;
    int wm = (wid >> 2) * 64, wn = (wid & 3) * 32;
    int bm = blockIdx.y * 128, bn = blockIdx.x * 128;

    float acc[4][4][4];
#pragma unroll
    for (int mt = 0; mt < 4; mt++)
#pragma unroll
        for (int nt = 0; nt < 4; nt++)
#pragma unroll
            for (int i = 0; i < 4; i++) acc[mt][nt][i] = 0.f;

    // staging: 128 rows x 32 cols each, 2 threads/row, 16 floats/thread
    int sRow = tid >> 1, sCol0 = (tid & 1) * 16;
    const float* Agp = A  + (size_t)(bm + sRow) * K + sCol0;
    const float* Wgp = Wt + (size_t)(bn + sRow) * K + sCol0;

    // ldmatrix bases
    uint32_t aLdsmBase = (uint32_t)__cvta_generic_to_shared(
        &As[wm + (lane & 15)][(lane >> 4) * 4]);
    int bq = lane >> 3;
    uint32_t bLdsmBase0 = (uint32_t)__cvta_generic_to_shared(
        &Bs[wn + (bq >> 1) * 8 + (lane & 7)][(bq & 1) * 4]);
    uint32_t bLdsmBase1 = bLdsmBase0 + 16u * 36u * 4u;   // +16 n-rows

    for (int k0 = 0; k0 < K; k0 += 32) {
#pragma unroll
        for (int p = 0; p < 4; p++) {
            float4 av = *(const float4*)(Agp + k0 + p * 4);
            uint4 u;
            u.x = f2tf32(av.x); u.y = f2tf32(av.y);
            u.z = f2tf32(av.z); u.w = f2tf32(av.w);
            *(uint4*)&As[sRow][sCol0 + p * 4] = u;
        }
#pragma unroll
        for (int p = 0; p < 4; p++) {
            float4 bv = *(const float4*)(Wgp + k0 + p * 4);
            uint4 u;
            u.x = f2tf32(bv.x); u.y = f2tf32(bv.y);
            u.z = f2tf32(bv.z); u.w = f2tf32(bv.w);
            *(uint4*)&Bs[sRow][sCol0 + p * 4] = u;
        }
        __syncthreads();
#pragma unroll
        for (int kt = 0; kt < 4; kt++) {
            int kb = kt * 8;
            uint32_t af[4][4], bf[4][2];
#pragma unroll
            for (int mt = 0; mt < 4; mt++)
                ldsm_x4(af[mt], aLdsmBase + (uint32_t)(mt * 16 * 36 + kb) * 4u);
            {
                uint32_t r[4];
                ldsm_x4(r, bLdsmBase0 + (uint32_t)kb * 4u);
                bf[0][0] = r[0]; bf[0][1] = r[1]; bf[1][0] = r[2]; bf[1][1] = r[3];
                ldsm_x4(r, bLdsmBase1 + (uint32_t)kb * 4u);
                bf[2][0] = r[0]; bf[2][1] = r[1]; bf[3][0] = r[2]; bf[3][1] = r[3];
            }
#pragma unroll
            for (int mt = 0; mt < 4; mt++)
#pragma unroll
                for (int nt = 0; nt < 4; nt++)
                    mma_tf32(acc[mt][nt], af[mt], bf[nt]);
        }
        __syncthreads();
    }

    // epilogue: c0:(g,tig*2) c1:(g,tig*2+1) c2:(g+8,tig*2) c3:(g+8,tig*2+1)
#pragma unroll
    for (int mt = 0; mt < 4; mt++) {
        int row0 = bm + wm + mt * 16 + g;
#pragma unroll
        for (int nt = 0; nt < 4; nt++) {
            int col = bn + wn + nt * 8 + tig * 2;
            float b0 = bias[col], b1 = bias[col + 1];
#pragma unroll
            for (int half = 0; half < 2; half++) {
                int row = row0 + half * 8;
                float v0 = acc[mt][nt][half * 2 + 0] + b0;
                float v1 = acc[mt][nt][half * 2 + 1] + b1;
                if (EPI == 1) { v0 = mishf(v0); v1 = mishf(v1); }
                if (EPI == 2) {
                    v0 += resid[(size_t)row * N + col];
                    v1 += resid[(size_t)row * N + col + 1];
                }
                C[(size_t)row * N + col]     = v0;
                C[(size_t)row * N + col + 1] = v1;
            }
        }
    }
}

// ---------------- fused attention: tf32 MMA scores + 1.5-entmax + tf32 MMA P@V ------
// (validated at R7/R9; unchanged)
#define ATT_PITCH 1028
#define ATT_SC_FLOATS (32*ATT_PITCH)              // 32896
#define ATT_QS_OFF ATT_SC_FLOATS
#define ATT_KV_OFF (ATT_QS_OFF + 32*68)           // 35072
#define ATT_SMEM_FLOATS (ATT_KV_OFF + 128*72)     // 44288
#define ATTN_SMEM_BYTES (ATT_SMEM_FLOATS*4)       // 177152
#define RED_PITCH 68
#define RED_WSTR (32*RED_PITCH)                   // 2176

__global__ __launch_bounds__(256)
void attn_kernel(const float* __restrict__ Q, const float* __restrict__ Kg,
                 const float* __restrict__ V, float* __restrict__ O) {
    extern __shared__ float sm[];
    float* sc = sm;                                    // [32][1028]
    uint32_t* qs  = (uint32_t*)(sm + ATT_QS_OFF);      // [32][68] tf32 (m-major)
    uint32_t* kvs = (uint32_t*)(sm + ATT_KV_OFF);      // K:[64][136] / V:[128][72] tf32

    int bh = blockIdx.y; int b = bh >> 4, h = bh & 15;
    int m0 = blockIdx.x * 32;
    const float* Qb = Q + (size_t)b * SS * DD + h * HDIM;
    const float* Kb = Kg + (size_t)b * SS * DD + h * HDIM;
    const float* Vb = V + (size_t)b * SS * DD + h * HDIM;

    int t = threadIdx.x, lane = t & 31, w = t >> 5;
    int g = lane >> 2, tig = lane & 3;

    // ---- stage Q (32x64) as tf32, [m][k] pitch 68 ----
    {
        int row = t >> 3, cb = (t & 7) * 8;
        const float* Qr = Qb + (size_t)(m0 + row) * DD + cb;
#pragma unroll
        for (int i = 0; i < 2; i++) {
            float4 qv = *(const float4*)(Qr + i * 4);
            qs[row * 68 + cb + i * 4 + 0] = f2tf32(qv.x);
            qs[row * 68 + cb + i * 4 + 1] = f2tf32(qv.y);
            qs[row * 68 + cb + i * 4 + 2] = f2tf32(qv.z);
            qs[row * 68 + cb + i * 4 + 3] = f2tf32(qv.w);
        }
    }
    __syncthreads();

    // ---- phase 1: S = scale * Q K^T via MMA; warp w owns cols [w*16, w*16+16) ----
    for (int n0 = 0; n0 < SS; n0 += 128) {
        {
            int n = t & 127, dh = (t >> 7) * 32;
            const float* Kr = Kb + (size_t)(n0 + n) * DD + dh;
#pragma unroll
            for (int i = 0; i < 8; i++) {
                float4 kvv = *(const float4*)(Kr + i * 4);
                kvs[(dh + i * 4 + 0) * 136 + n] = f2tf32(kvv.x);
                kvs[(dh + i * 4 + 1) * 136 + n] = f2tf32(kvv.y);
                kvs[(dh + i * 4 + 2) * 136 + n] = f2tf32(kvv.z);
                kvs[(dh + i * 4 + 3) * 136 + n] = f2tf32(kvv.w);
            }
        }
        __syncthreads();
        float acc[2][2][4];
#pragma unroll
        for (int mt = 0; mt < 2; mt++)
#pragma unroll
            for (int nt = 0; nt < 2; nt++)
#pragma unroll
                for (int i = 0; i < 4; i++) acc[mt][nt][i] = 0.f;
        int nb = w * 16;
#pragma unroll
        for (int ks = 0; ks < 8; ks++) {
            int kb = ks * 8;
            uint32_t af[2][4], bf[2][2];
#pragma unroll
            for (int mt = 0; mt < 2; mt++) {
                int row = mt * 16 + g;
                af[mt][0] = qs[row * 68 + kb + tig];
                af[mt][1] = qs[(row + 8) * 68 + kb + tig];
                af[mt][2] = qs[row * 68 + kb + tig + 4];
                af[mt][3] = qs[(row + 8) * 68 + kb + tig + 4];
            }
#pragma unroll
            for (int nt = 0; nt < 2; nt++) {
                int n = nb + nt * 8 + g;
                bf[nt][0] = kvs[(kb + tig) * 136 + n];
                bf[nt][1] = kvs[(kb + tig + 4) * 136 + n];
            }
#pragma unroll
            for (int mt = 0; mt < 2; mt++)
#pragma unroll
                for (int nt = 0; nt < 2; nt++)
                    mma_tf32(acc[mt][nt], af[mt], bf[nt]);
        }
#pragma unroll
        for (int mt = 0; mt < 2; mt++) {
            int row = mt * 16 + g;
#pragma unroll
            for (int nt = 0; nt < 2; nt++) {
                int col = n0 + nb + nt * 8 + tig * 2;
                sc[row * ATT_PITCH + col]           = acc[mt][nt][0] * ATT_SCALE;
                sc[row * ATT_PITCH + col + 1]       = acc[mt][nt][1] * ATT_SCALE;
                sc[(row + 8) * ATT_PITCH + col]     = acc[mt][nt][2] * ATT_SCALE;
                sc[(row + 8) * ATT_PITCH + col + 1] = acc[mt][nt][3] * ATT_SCALE;
            }
        }
        __syncthreads();
    }

    // ---- phase 2: exact 1.5-entmax per row (warp w owns rows 4w..4w+3) ----
#pragma unroll 1
    for (int r = 0; r < 4; r++) {
        float* z = sc + (size_t)(w * 4 + r) * ATT_PITCH;
        float v[32];
#pragma unroll
        for (int i = 0; i < 32; i++) v[i] = z[lane + 32 * i];
        float m = -1e30f;
#pragma unroll
        for (int i = 0; i < 32; i++) m = fmaxf(m, v[i]);
        m = warpMax(m);
#pragma unroll
        for (int i = 0; i < 32; i++) v[i] = (v[i] - m) * 0.5f;
        float lo = -1.f, hi = 0.f;
        for (int it = 0; it < 30; it++) {
            float tau = 0.5f * (lo + hi);
            float s = 0.f;
#pragma unroll
            for (int i = 0; i < 32; i++) {
                float d = v[i] - tau;
                if (d > 0.f) s = fmaf(d, d, s);
            }
            s = warpSum(s);
            if (s >= 1.f) lo = tau; else hi = tau;
        }
        float tau = 0.5f * (lo + hi);
#pragma unroll
        for (int i = 0; i < 32; i++) {
            float d = v[i] - tau;
            d = d > 0.f ? d : 0.f;
            z[lane + 32 * i] = d * d;
        }
    }
    __syncthreads();

    // ---- phase 3: O = P V via MMA; warp w covers k-slice [w*16, w*16+16) per chunk ----
    float oacc[2][8][4];
#pragma unroll
    for (int mt = 0; mt < 2; mt++)
#pragma unroll
        for (int nt = 0; nt < 8; nt++)
#pragma unroll
            for (int i = 0; i < 4; i++) oacc[mt][nt][i] = 0.f;

    for (int c = 0; c < 8; c++) {
        int k0 = c * 128;
        {
            int r = t >> 1, ch = (t & 1) * 32;
            const float* Vr = Vb + (size_t)(k0 + r) * DD + ch;
#pragma unroll
            for (int i = 0; i < 8; i++) {
                float4 vv = *(const float4*)(Vr + i * 4);
                uint4 u;
                u.x = f2tf32(vv.x); u.y = f2tf32(vv.y);
                u.z = f2tf32(vv.z); u.w = f2tf32(vv.w);
                *(uint4*)&kvs[r * 72 + ch + i * 4] = u;
            }
        }
        __syncthreads();
#pragma unroll
        for (int s = 0; s < 2; s++) {
            int kb = w * 16 + s * 8;
            uint32_t af[2][4];
#pragma unroll
            for (int mt = 0; mt < 2; mt++) {
                int row = mt * 16 + g;
                af[mt][0] = f2tf32(sc[row * ATT_PITCH + k0 + kb + tig]);
                af[mt][1] = f2tf32(sc[(row + 8) * ATT_PITCH + k0 + kb + tig]);
                af[mt][2] = f2tf32(sc[row * ATT_PITCH + k0 + kb + tig + 4]);
                af[mt][3] = f2tf32(sc[(row + 8) * ATT_PITCH + k0 + kb + tig + 4]);
            }
#pragma unroll
            for (int nt = 0; nt < 8; nt++) {
                uint32_t bf[2];
                bf[0] = kvs[(kb + tig) * 72 + nt * 8 + g];
                bf[1] = kvs[(kb + tig + 4) * 72 + nt * 8 + g];
#pragma unroll
                for (int mt = 0; mt < 2; mt++)
                    mma_tf32(oacc[mt][nt], af[mt], bf);
            }
        }
        __syncthreads();
    }

    // ---- reduce 8 warp-partials through smem (sc is free now) ----
#pragma unroll
    for (int mt = 0; mt < 2; mt++) {
        int row = mt * 16 + g;
#pragma unroll
        for (int nt = 0; nt < 8; nt++) {
            int col = nt * 8 + tig * 2;
            float* pb = sc + w * RED_WSTR;
            pb[row * RED_PITCH + col]           = oacc[mt][nt][0];
            pb[row * RED_PITCH + col + 1]       = oacc[mt][nt][1];
            pb[(row + 8) * RED_PITCH + col]     = oacc[mt][nt][2];
            pb[(row + 8) * RED_PITCH + col + 1] = oacc[mt][nt][3];
        }
    }
    __syncthreads();
    float* Ob = O + (size_t)b * SS * DD + h * HDIM;
#pragma unroll
    for (int i = 0; i < 8; i++) {
        int idx = i * 256 + t;          // 0..2047
        int mm = idx >> 6, dd = idx & 63;
        float sum = 0.f;
#pragma unroll
        for (int ww = 0; ww < 8; ww++)
            sum += sc[ww * RED_WSTR + mm * RED_PITCH + dd];
        Ob[(size_t)(m0 + mm) * DD + dd] = sum;
    }
}

// ---------------- launch ----------------
extern "C" void kernel_launch(void* const* d_in, const int* in_sizes, int n_in,
                              void* d_out, int out_size) {
    const float* x = (const float*)d_in[0];
    const float *wq, *bq, *wk, *bk, *wv, *bv, *wo, *bo;
    if (in_sizes[2] == DD) {
        wq = (const float*)d_in[1]; bq = (const float*)d_in[2];
        wk = (const float*)d_in[3]; bk = (const float*)d_in[4];
        wv = (const float*)d_in[5]; bv = (const float*)d_in[6];
        wo = (const float*)d_in[7]; bo = (const float*)d_in[8];
    } else {
        wq = (const float*)d_in[1]; wk = (const float*)d_in[2];
        wv = (const float*)d_in[3]; wo = (const float*)d_in[4];
        bq = (const float*)d_in[5]; bk = (const float*)d_in[6];
        bv = (const float*)d_in[7]; bo = (const float*)d_in[8];
    }
    const float* w_up   = (const float*)d_in[9];
    const float* b_up   = (const float*)d_in[10];
    const float* w_down = (const float*)d_in[11];
    const float* b_down = (const float*)d_in[12];
    const float* ln1g = (const float*)d_in[13];
    const float* ln1b = (const float*)d_in[14];
    const float* ln2g = (const float*)d_in[15];
    const float* ln2b = (const float*)d_in[16];
    const float* lnfg = (const float*)d_in[17];
    const float* lnfb = (const float*)d_in[18];

    float *yp, *qp, *kp, *vp, *x1p, *hp, *wtp;
    cudaGetSymbolAddress((void**)&yp,  g_y);
    cudaGetSymbolAddress((void**)&qp,  g_q);
    cudaGetSymbolAddress((void**)&kp,  g_k);
    cudaGetSymbolAddress((void**)&vp,  g_v);
    cudaGetSymbolAddress((void**)&x1p, g_x1);
    cudaGetSymbolAddress((void**)&hp,  g_h);
    cudaGetSymbolAddress((void**)&wtp, g_wt);
    float* op  = yp;   // reuse: y dead after V projection
    float* x2p = qp;   // reuse: q dead after attention
    float* wqT = wtp + WT_Q;
    float* wkT = wtp + WT_K;
    float* wvT = wtp + WT_V;
    float* woT = wtp + WT_O;
    float* wbig = wtp + WT_BIG;   // w_upT, then reused for w_downT

    cudaFuncSetAttribute(attn_kernel, cudaFuncAttributeMaxDynamicSharedMemorySize,
                         ATTN_SMEM_BYTES);

    dim3 tb(32, 8);
    // 0. transpose attention weights
    transpose_kernel<<<dim3(DD/32, DD/32), tb>>>(wq, wqT, DD, DD);
    transpose_kernel<<<dim3(DD/32, DD/32), tb>>>(wk, wkT, DD, DD);
    transpose_kernel<<<dim3(DD/32, DD/32), tb>>>(wv, wvT, DD, DD);
    transpose_kernel<<<dim3(DD/32, DD/32), tb>>>(wo, woT, DD, DD);
    // 1. ln1
    ln_kernel<<<NROWS, 256>>>(x, ln1g, ln1b, yp);
    // 2-4. Q,K,V projections
    tgemm_kernel<0><<<dim3(8, 32), 256>>>(yp, wqT, bq, nullptr, qp, NROWS, DD, DD);
    tgemm_kernel<0><<<dim3(8, 32), 256>>>(yp, wkT, bk, nullptr, kp, NROWS, DD, DD);
    tgemm_kernel<0><<<dim3(8, 32), 256>>>(yp, wvT, bv, nullptr, vp, NROWS, DD, DD);
    // 5. fused attention (MMA scores + entmax + MMA P@V)
    attn_kernel<<<dim3(SS / 32, NHEADS), 256, ATTN_SMEM_BYTES>>>(qp, kp, vp, op);
    // 6. out proj + residual
    tgemm_kernel<2><<<dim3(8, 32), 256>>>(op, woT, bo, x, x1p, NROWS, DD, DD);
    // 7. ln2 -> k scratch (k dead)
    ln_kernel<<<NROWS, 256>>>(x1p, ln2g, ln2b, kp);
    // 8. FFN up + mish (transpose w_up first)
    transpose_kernel<<<dim3(FF/32, DD/32), tb>>>(w_up, wbig, DD, FF);
    tgemm_kernel<1><<<dim3(32, 32), 256>>>(kp, wbig, b_up, nullptr, hp, NROWS, FF, DD);
    // 9. FFN down + residual (w_upT dead; reuse wbig)
    transpose_kernel<<<dim3(DD/32, FF/32), tb>>>(w_down, wbig, FF, DD);
    tgemm_kernel<2><<<dim3(8, 32), 256>>>(hp, wbig, b_down, x1p, x2p, NROWS, DD, FF);
    // 10. final ln -> out
    ln_kernel<<<NROWS, 256>>>(x2p, lnfg, lnfb, (float*)d_out);
}

// round 12
// speedup vs baseline: 1.1977x; 1.1896x over previous
#include <cuda_runtime.h>
#include <math.h>
#include <stdint.h>

#define BB 4
#define SS 1024
#define DD 1024
#define HH 16
#define HDIM 64
#define FF 4096
#define NROWS (BB*SS)           // 4096
#define NHEADS (BB*HH)          // 64
#define LN_EPS 1e-5f
#define ATT_SCALE 0.125f        // 1/sqrt(64)

// ---------------- scratch (static device arrays; no cudaMalloc allowed) --------------
__device__ float g_y [NROWS*DD];   // ln1 out, later attention output
__device__ float g_q [NROWS*DD];   // Q, later x2 (post-FFN residual)
__device__ float g_k [NROWS*DD];
__device__ float g_v [NROWS*DD];
__device__ float g_x1[NROWS*DD];   // post-attention residual
__device__ float g_h [NROWS*FF];   // FFN hidden

// ---------------- helpers ----------------
__device__ __forceinline__ float warpSum(float v) {
#pragma unroll
    for (int o = 16; o > 0; o >>= 1) v += __shfl_xor_sync(0xffffffffu, v, o);
    return v;
}
__device__ __forceinline__ float warpMax(float v) {
#pragma unroll
    for (int o = 16; o > 0; o >>= 1) v = fmaxf(v, __shfl_xor_sync(0xffffffffu, v, o));
    return v;
}
__device__ __forceinline__ uint32_t f2tf32(float x) {
    uint32_t r;
    asm("cvt.rna.tf32.f32 %0, %1;" : "=r"(r) : "f"(x));
    return r;
}
__device__ __forceinline__ void mma_tf32(float* c, const uint32_t* a, const uint32_t* b) {
    asm volatile(
        "mma.sync.aligned.m16n8k8.row.col.f32.tf32.tf32.f32 "
        "{%0,%1,%2,%3}, {%4,%5,%6,%7}, {%8,%9}, {%0,%1,%2,%3};\n"
        : "+f"(c[0]), "+f"(c[1]), "+f"(c[2]), "+f"(c[3])
        : "r"(a[0]), "r"(a[1]), "r"(a[2]), "r"(a[3]), "r"(b[0]), "r"(b[1]));
}
__device__ __forceinline__ void ldsm_x4(uint32_t* r, uint32_t addr) {
    asm volatile("ldmatrix.sync.aligned.m8n8.x4.shared.b16 {%0,%1,%2,%3}, [%4];"
                 : "=r"(r[0]), "=r"(r[1]), "=r"(r[2]), "=r"(r[3]) : "r"(addr));
}

// ---------------- LayerNorm over D=1024, one block (256 thr) per row -----------------
__global__ void ln_kernel(const float* __restrict__ in, const float* __restrict__ g,
                          const float* __restrict__ b, float* __restrict__ out) {
    int row = blockIdx.x;
    const float* x = in + (size_t)row * DD;
    int t = threadIdx.x, lane = t & 31, wid = t >> 5;
    float v[4];
#pragma unroll
    for (int i = 0; i < 4; i++) v[i] = x[t + 256 * i];
    float s = v[0] + v[1] + v[2] + v[3];
    float ss = v[0]*v[0] + v[1]*v[1] + v[2]*v[2] + v[3]*v[3];
    s = warpSum(s); ss = warpSum(ss);
    __shared__ float rA[8], rB[8];
    if (lane == 0) { rA[wid] = s; rB[wid] = ss; }
    __syncthreads();
    s  = (lane < 8) ? rA[lane] : 0.f;
    ss = (lane < 8) ? rB[lane] : 0.f;
    s = warpSum(s); ss = warpSum(ss);
    float mean = s * (1.f / DD);
    float var  = ss * (1.f / DD) - mean * mean;
    float rstd = rsqrtf(var + LN_EPS);
    float* o = out + (size_t)row * DD;
#pragma unroll
    for (int i = 0; i < 4; i++) {
        int c = t + 256 * i;
        o[c] = (v[i] - mean) * rstd * g[c] + b[c];
    }
}

__device__ __forceinline__ float mishf(float x) {
    float sp = (x > 20.f) ? x : log1pf(expf(x));
    return x * tanhf(sp);
}

// ---------------- tf32 tensor-core GEMM with ldmatrix A-fragments (R9-validated) -----
// Block tile 128x128, BK=32. 8 warps in 2(m) x 4(n): each warp 64x32 = 4x4 m16n8k8.
// As: [m][k] tf32, pitch 36 (rows 16B-aligned; ldmatrix chunk stride 9 mod 8 -> CF).
// Bs: [k][n] tf32, pitch 136 (scalar frag gather 8*tig+g -> CF).
template <int EPI>
__global__ __launch_bounds__(256)
void tgemm_kernel(const float* __restrict__ A, const float* __restrict__ W,
                  const float* __restrict__ bias, const float* __restrict__ resid,
                  float* __restrict__ C, int M, int N, int K) {
    __shared__ uint32_t As[128][36];   // [m][k]
    __shared__ uint32_t Bs[32][136];   // [k][n]
    int tid = threadIdx.x, lane = tid & 31, wid = tid >> 5;
    int g = lane >> 2, tig = lane & 3;
    int wm = (wid >> 2) * 64, wn = (wid & 3) * 32;
    int bm = blockIdx.y * 128, bn = blockIdx.x * 128;

    float acc[4][4][4];
#pragma unroll
    for (int mt = 0; mt < 4; mt++)
#pragma unroll
        for (int nt = 0; nt < 4; nt++)
#pragma unroll
            for (int i = 0; i < 4; i++) acc[mt][nt][i] = 0.f;

    // staging maps
    int aRow = tid >> 1, aCol0 = (tid & 1) * 16;    // A: 128 rows x 32 cols, 2 thr/row
    int bRow = tid >> 3, bColB = (tid & 7) * 4;     // B: 32 rows x 128 cols
    const float* Ab = A + (size_t)(bm + aRow) * K + aCol0;
    const float* Wb = W + (size_t)bRow * N + bn;

    // per-lane ldmatrix base: row (lane&15) within warp m-range, col half (lane>>4)*4
    uint32_t aLdsmBase = (uint32_t)__cvta_generic_to_shared(
        &As[wm + (lane & 15)][(lane >> 4) * 4]);

    for (int k0 = 0; k0 < K; k0 += 32) {
        // stage A [m][k] (cvt to tf32, STS.128)
#pragma unroll
        for (int p = 0; p < 4; p++) {
            float4 av = *(const float4*)(Ab + k0 + p * 4);
            uint4 u;
            u.x = f2tf32(av.x); u.y = f2tf32(av.y);
            u.z = f2tf32(av.z); u.w = f2tf32(av.w);
            *(uint4*)&As[aRow][aCol0 + p * 4] = u;
        }
        // stage B [k][n]
#pragma unroll
        for (int p = 0; p < 4; p++) {
            float4 bv = *(const float4*)(Wb + (size_t)k0 * N + bColB + p * 32);
            uint4 u;
            u.x = f2tf32(bv.x); u.y = f2tf32(bv.y);
            u.z = f2tf32(bv.z); u.w = f2tf32(bv.w);
            *(uint4*)&Bs[bRow][bColB + p * 32] = u;
        }
        __syncthreads();
#pragma unroll
        for (int kt = 0; kt < 4; kt++) {
            int kb = kt * 8;
            uint32_t af[4][4], bf[4][2];
#pragma unroll
            for (int mt = 0; mt < 4; mt++)
                ldsm_x4(af[mt], aLdsmBase + (uint32_t)(mt * 16 * 36 + kb) * 4u);
#pragma unroll
            for (int nt = 0; nt < 4; nt++) {
                int n = wn + nt * 8 + g;
                bf[nt][0] = Bs[kb + tig][n];
                bf[nt][1] = Bs[kb + tig + 4][n];
            }
#pragma unroll
            for (int mt = 0; mt < 4; mt++)
#pragma unroll
                for (int nt = 0; nt < 4; nt++)
                    mma_tf32(acc[mt][nt], af[mt], bf[nt]);
        }
        __syncthreads();
    }

    // epilogue: c0:(g,tig*2) c1:(g,tig*2+1) c2:(g+8,tig*2) c3:(g+8,tig*2+1)
#pragma unroll
    for (int mt = 0; mt < 4; mt++) {
        int row0 = bm + wm + mt * 16 + g;
#pragma unroll
        for (int nt = 0; nt < 4; nt++) {
            int col = bn + wn + nt * 8 + tig * 2;
            float b0 = bias[col], b1 = bias[col + 1];
#pragma unroll
            for (int half = 0; half < 2; half++) {
                int row = row0 + half * 8;
                float v0 = acc[mt][nt][half * 2 + 0] + b0;
                float v1 = acc[mt][nt][half * 2 + 1] + b1;
                if (EPI == 1) { v0 = mishf(v0); v1 = mishf(v1); }
                if (EPI == 2) {
                    v0 += resid[(size_t)row * N + col];
                    v1 += resid[(size_t)row * N + col + 1];
                }
                C[(size_t)row * N + col]     = v0;
                C[(size_t)row * N + col + 1] = v1;
            }
        }
    }
}

// ---------------- fused attention: tf32 MMA scores + 1.5-entmax (Newton) + MMA P@V --
#define ATT_PITCH 1028
#define ATT_SC_FLOATS (32*ATT_PITCH)              // 32896
#define ATT_QS_OFF ATT_SC_FLOATS
#define ATT_KV_OFF (ATT_QS_OFF + 32*68)           // 35072
#define ATT_SMEM_FLOATS (ATT_KV_OFF + 128*72)     // 44288
#define ATTN_SMEM_BYTES (ATT_SMEM_FLOATS*4)       // 177152
#define RED_PITCH 68
#define RED_WSTR (32*RED_PITCH)                   // 2176

__global__ __launch_bounds__(256)
void attn_kernel(const float* __restrict__ Q, const float* __restrict__ Kg,
                 const float* __restrict__ V, float* __restrict__ O) {
    extern __shared__ float sm[];
    float* sc = sm;                                    // [32][1028]
    uint32_t* qs  = (uint32_t*)(sm + ATT_QS_OFF);      // [32][68] tf32 (m-major)
    uint32_t* kvs = (uint32_t*)(sm + ATT_KV_OFF);      // K:[64][136] / V:[128][72] tf32

    int bh = blockIdx.y; int b = bh >> 4, h = bh & 15;
    int m0 = blockIdx.x * 32;
    const float* Qb = Q + (size_t)b * SS * DD + h * HDIM;
    const float* Kb = Kg + (size_t)b * SS * DD + h * HDIM;
    const float* Vb = V + (size_t)b * SS * DD + h * HDIM;

    int t = threadIdx.x, lane = t & 31, w = t >> 5;
    int g = lane >> 2, tig = lane & 3;

    // ---- stage Q (32x64) as tf32, [m][k] pitch 68 ----
    {
        int row = t >> 3, cb = (t & 7) * 8;
        const float* Qr = Qb + (size_t)(m0 + row) * DD + cb;
#pragma unroll
        for (int i = 0; i < 2; i++) {
            float4 qv = *(const float4*)(Qr + i * 4);
            qs[row * 68 + cb + i * 4 + 0] = f2tf32(qv.x);
            qs[row * 68 + cb + i * 4 + 1] = f2tf32(qv.y);
            qs[row * 68 + cb + i * 4 + 2] = f2tf32(qv.z);
            qs[row * 68 + cb + i * 4 + 3] = f2tf32(qv.w);
        }
    }
    __syncthreads();

    // ---- phase 1: S = scale * Q K^T via MMA; warp w owns cols [w*16, w*16+16) ----
    for (int n0 = 0; n0 < SS; n0 += 128) {
        {
            int n = t & 127, dh = (t >> 7) * 32;
            const float* Kr = Kb + (size_t)(n0 + n) * DD + dh;
#pragma unroll
            for (int i = 0; i < 8; i++) {
                float4 kvv = *(const float4*)(Kr + i * 4);
                kvs[(dh + i * 4 + 0) * 136 + n] = f2tf32(kvv.x);
                kvs[(dh + i * 4 + 1) * 136 + n] = f2tf32(kvv.y);
                kvs[(dh + i * 4 + 2) * 136 + n] = f2tf32(kvv.z);
                kvs[(dh + i * 4 + 3) * 136 + n] = f2tf32(kvv.w);
            }
        }
        __syncthreads();
        float acc[2][2][4];
#pragma unroll
        for (int mt = 0; mt < 2; mt++)
#pragma unroll
            for (int nt = 0; nt < 2; nt++)
#pragma unroll
                for (int i = 0; i < 4; i++) acc[mt][nt][i] = 0.f;
        int nb = w * 16;
#pragma unroll
        for (int ks = 0; ks < 8; ks++) {
            int kb = ks * 8;
            uint32_t af[2][4], bf[2][2];
#pragma unroll
            for (int mt = 0; mt < 2; mt++) {
                int row = mt * 16 + g;
                af[mt][0] = qs[row * 68 + kb + tig];
                af[mt][1] = qs[(row + 8) * 68 + kb + tig];
                af[mt][2] = qs[row * 68 + kb + tig + 4];
                af[mt][3] = qs[(row + 8) * 68 + kb + tig + 4];
            }
#pragma unroll
            for (int nt = 0; nt < 2; nt++) {
                int n = nb + nt * 8 + g;
                bf[nt][0] = kvs[(kb + tig) * 136 + n];
                bf[nt][1] = kvs[(kb + tig + 4) * 136 + n];
            }
#pragma unroll
            for (int mt = 0; mt < 2; mt++)
#pragma unroll
                for (int nt = 0; nt < 2; nt++)
                    mma_tf32(acc[mt][nt], af[mt], bf[nt]);
        }
#pragma unroll
        for (int mt = 0; mt < 2; mt++) {
            int row = mt * 16 + g;
#pragma unroll
            for (int nt = 0; nt < 2; nt++) {
                int col = n0 + nb + nt * 8 + tig * 2;
                sc[row * ATT_PITCH + col]           = acc[mt][nt][0] * ATT_SCALE;
                sc[row * ATT_PITCH + col + 1]       = acc[mt][nt][1] * ATT_SCALE;
                sc[(row + 8) * ATT_PITCH + col]     = acc[mt][nt][2] * ATT_SCALE;
                sc[(row + 8) * ATT_PITCH + col + 1] = acc[mt][nt][3] * ATT_SCALE;
            }
        }
        __syncthreads();
    }

    // ---- phase 2: exact 1.5-entmax per row; tau via Newton (convex f, monotone) ----
#pragma unroll 1
    for (int r = 0; r < 4; r++) {
        float* z = sc + (size_t)(w * 4 + r) * ATT_PITCH;
        float v[32];
#pragma unroll
        for (int i = 0; i < 32; i++) v[i] = z[lane + 32 * i];
        float m = -1e30f;
#pragma unroll
        for (int i = 0; i < 32; i++) m = fmaxf(m, v[i]);
        m = warpMax(m);
#pragma unroll
        for (int i = 0; i < 32; i++) v[i] = (v[i] - m) * 0.5f;
        // f(tau) = sum relu(v-tau)^2 is convex decreasing; Newton from tau=-1
        // stays on the f>=1 side and increases monotonically to tau* (<= -1/32).
        float tau = -1.f;
#pragma unroll 1
        for (int it = 0; it < 8; it++) {
            float S1 = 0.f, S2 = 0.f;
#pragma unroll
            for (int i = 0; i < 32; i++) {
                float d = v[i] - tau;
                if (d > 0.f) { S1 += d; S2 = fmaf(d, d, S2); }
            }
#pragma unroll
            for (int o = 16; o > 0; o >>= 1) {
                S1 += __shfl_xor_sync(0xffffffffu, S1, o);
                S2 += __shfl_xor_sync(0xffffffffu, S2, o);
            }
            if (S1 < 1e-12f) break;
            tau += (S2 - 1.f) / (2.f * S1);
        }
#pragma unroll
        for (int i = 0; i < 32; i++) {
            float d = v[i] - tau;
            d = d > 0.f ? d : 0.f;
            z[lane + 32 * i] = d * d;
        }
    }
    __syncthreads();

    // ---- phase 3: O = P V via MMA; warp w covers k-slice [w*16, w*16+16) per chunk ----
    float oacc[2][8][4];
#pragma unroll
    for (int mt = 0; mt < 2; mt++)
#pragma unroll
        for (int nt = 0; nt < 8; nt++)
#pragma unroll
            for (int i = 0; i < 4; i++) oacc[mt][nt][i] = 0.f;

    for (int c = 0; c < 8; c++) {
        int k0 = c * 128;
        {
            int r = t >> 1, ch = (t & 1) * 32;
            const float* Vr = Vb + (size_t)(k0 + r) * DD + ch;
#pragma unroll
            for (int i = 0; i < 8; i++) {
                float4 vv = *(const float4*)(Vr + i * 4);
                uint4 u;
                u.x = f2tf32(vv.x); u.y = f2tf32(vv.y);
                u.z = f2tf32(vv.z); u.w = f2tf32(vv.w);
                *(uint4*)&kvs[r * 72 + ch + i * 4] = u;
            }
        }
        __syncthreads();
#pragma unroll
        for (int s = 0; s < 2; s++) {
            int kb = w * 16 + s * 8;
            uint32_t af[2][4];
#pragma unroll
            for (int mt = 0; mt < 2; mt++) {
                int row = mt * 16 + g;
                af[mt][0] = f2tf32(sc[row * ATT_PITCH + k0 + kb + tig]);
                af[mt][1] = f2tf32(sc[(row + 8) * ATT_PITCH + k0 + kb + tig]);
                af[mt][2] = f2tf32(sc[row * ATT_PITCH + k0 + kb + tig + 4]);
                af[mt][3] = f2tf32(sc[(row + 8) * ATT_PITCH + k0 + kb + tig + 4]);
            }
#pragma unroll
            for (int nt = 0; nt < 8; nt++) {
                uint32_t bf[2];
                bf[0] = kvs[(kb + tig) * 72 + nt * 8 + g];
                bf[1] = kvs[(kb + tig + 4) * 72 + nt * 8 + g];
#pragma unroll
                for (int mt = 0; mt < 2; mt++)
                    mma_tf32(oacc[mt][nt], af[mt], bf);
            }
        }
        __syncthreads();
    }

    // ---- reduce 8 warp-partials through smem (sc is free now) ----
#pragma unroll
    for (int mt = 0; mt < 2; mt++) {
        int row = mt * 16 + g;
#pragma unroll
        for (int nt = 0; nt < 8; nt++) {
            int col = nt * 8 + tig * 2;
            float* pb = sc + w * RED_WSTR;
            pb[row * RED_PITCH + col]           = oacc[mt][nt][0];
            pb[row * RED_PITCH + col + 1]       = oacc[mt][nt][1];
            pb[(row + 8) * RED_PITCH + col]     = oacc[mt][nt][2];
            pb[(row + 8) * RED_PITCH + col + 1] = oacc[mt][nt][3];
        }
    }
    __syncthreads();
    float* Ob = O + (size_t)b * SS * DD + h * HDIM;
#pragma unroll
    for (int i = 0; i < 8; i++) {
        int idx = i * 256 + t;          // 0..2047
        int mm = idx >> 6, dd = idx & 63;
        float sum = 0.f;
#pragma unroll
        for (int ww = 0; ww < 8; ww++)
            sum += sc[ww * RED_WSTR + mm * RED_PITCH + dd];
        Ob[(size_t)(m0 + mm) * DD + dd] = sum;
    }
}

// ---------------- launch ----------------
extern "C" void kernel_launch(void* const* d_in, const int* in_sizes, int n_in,
                              void* d_out, int out_size) {
    const float* x = (const float*)d_in[0];
    const float *wq, *bq, *wk, *bk, *wv, *bv, *wo, *bo;
    if (in_sizes[2] == DD) {
        wq = (const float*)d_in[1]; bq = (const float*)d_in[2];
        wk = (const float*)d_in[3]; bk = (const float*)d_in[4];
        wv = (const float*)d_in[5]; bv = (const float*)d_in[6];
        wo = (const float*)d_in[7]; bo = (const float*)d_in[8];
    } else {
        wq = (const float*)d_in[1]; wk = (const float*)d_in[2];
        wv = (const float*)d_in[3]; wo = (const float*)d_in[4];
        bq = (const float*)d_in[5]; bk = (const float*)d_in[6];
        bv = (const float*)d_in[7]; bo = (const float*)d_in[8];
    }
    const float* w_up   = (const float*)d_in[9];
    const float* b_up   = (const float*)d_in[10];
    const float* w_down = (const float*)d_in[11];
    const float* b_down = (const float*)d_in[12];
    const float* ln1g = (const float*)d_in[13];
    const float* ln1b = (const float*)d_in[14];
    const float* ln2g = (const float*)d_in[15];
    const float* ln2b = (const float*)d_in[16];
    const float* lnfg = (const float*)d_in[17];
    const float* lnfb = (const float*)d_in[18];

    float *yp, *qp, *kp, *vp, *x1p, *hp;
    cudaGetSymbolAddress((void**)&yp,  g_y);
    cudaGetSymbolAddress((void**)&qp,  g_q);
    cudaGetSymbolAddress((void**)&kp,  g_k);
    cudaGetSymbolAddress((void**)&vp,  g_v);
    cudaGetSymbolAddress((void**)&x1p, g_x1);
    cudaGetSymbolAddress((void**)&hp,  g_h);
    float* op  = yp;   // reuse: y dead after V projection
    float* x2p = qp;   // reuse: q dead after attention

    cudaFuncSetAttribute(attn_kernel, cudaFuncAttributeMaxDynamicSharedMemorySize,
                         ATTN_SMEM_BYTES);

    // 1. ln1
    ln_kernel<<<NROWS, 256>>>(x, ln1g, ln1b, yp);
    // 2-4. Q,K,V projections
    tgemm_kernel<0><<<dim3(8, 32), 256>>>(yp, wq, bq, nullptr, qp, NROWS, DD, DD);
    tgemm_kernel<0><<<dim3(8, 32), 256>>>(yp, wk, bk, nullptr, kp, NROWS, DD, DD);
    tgemm_kernel<0><<<dim3(8, 32), 256>>>(yp, wv, bv, nullptr, vp, NROWS, DD, DD);
    // 5. fused attention (MMA scores + Newton entmax + MMA P@V)
    attn_kernel<<<dim3(SS / 32, NHEADS), 256, ATTN_SMEM_BYTES>>>(qp, kp, vp, op);
    // 6. out proj + residual
    tgemm_kernel<2><<<dim3(8, 32), 256>>>(op, wo, bo, x, x1p, NROWS, DD, DD);
    // 7. ln2 -> k scratch (k dead)
    ln_kernel<<<NROWS, 256>>>(x1p, ln2g, ln2b, kp);
    // 8. FFN up + mish
    tgemm_kernel<1><<<dim3(32, 32), 256>>>(kp, w_up, b_up, nullptr, hp, NROWS, FF, DD);
    // 9. FFN down + residual
    tgemm_kernel<2><<<dim3(8, 32), 256>>>(hp, w_down, b_down, x1p, x2p, NROWS, DD, FF);
    // 10. final ln -> out
    ln_kernel<<<NROWS, 256>>>(x2p, lnfg, lnfb, (float*)d_out);
}